// round 10
// baseline (speedup 1.0000x reference)
#include <cuda_runtime.h>
#include <math.h>

#define CIN   1024
#define COUT  512
#define NPIX  4096
#define NANCH 36864
#define SORTN 65536
#define NPRE  12000
#define NPOST 2000
#define NWORD 188   /* ceil(12000/64) */

#define OFF_LOC  0
#define OFF_SC   147456
#define OFF_ROIS 221184
#define OFF_ANC  229184

typedef unsigned long long u64;

__device__ __align__(16) float g_h[COUT * NPIX];        // conv output, 8 MB
__device__ __align__(16) float g_wt[9216 * 512];        // transposed conv weights [j][oc]
__device__ __align__(16) float g_wh[COUT * 56];         // transposed head weights
__device__ __align__(16) float g_boxes[NANCH * 4];      // decoded boxes
__device__ u64 g_keys[SORTN];                           // sort keys
__device__ __align__(16) float g_sboxes[NPRE * 4];      // clipped sorted boxes
__device__ int g_valid[NPRE];
__device__ u64 g_mask[(size_t)NPRE * NWORD];            // NMS bitmask, 18 MB

// packed f32x2 helpers
#define FMA2(d, a, b) asm("fma.rn.f32x2 %0, %1, %2, %0;" : "+l"(d) : "l"(a), "l"(b))
#define ADD2(d, a, b) asm("add.rn.f32x2 %0, %1, %2;" : "=l"(d) : "l"(a), "l"(b))
#define PK2(d, lo, hi) asm("mov.b64 %0, {%1, %2};" : "=l"(d) : "f"(lo), "f"(hi))
#define UPK2(lo, hi, s) asm("mov.b64 {%0, %1}, %2;" : "=f"(lo), "=f"(hi) : "l"(s))
#define NEGMASK2 0x8000000080000000ull

// ---------------------------------------------------------------------------
// transpose conv weights: w[512][9216] -> g_wt[9216][512]
// ---------------------------------------------------------------------------
__global__ void __launch_bounds__(256) prep_wt(const float* __restrict__ w) {
    __shared__ float tile[32][33];
    const int j0  = blockIdx.x * 32;
    const int oc0 = blockIdx.y * 32;
    const int tx = threadIdx.x & 31, ty = threadIdx.x >> 5;
#pragma unroll
    for (int r = 0; r < 4; ++r)
        tile[ty + r * 8][tx] = w[(size_t)(oc0 + ty + r * 8) * 9216 + j0 + tx];
    __syncthreads();
#pragma unroll
    for (int r = 0; r < 4; ++r)
        g_wt[(size_t)(j0 + ty + r * 8) * 512 + oc0 + tx] = tile[tx][ty + r * 8];
}

// ---------------------------------------------------------------------------
__global__ void prep_w(const float* __restrict__ score_w, const float* __restrict__ loc_w) {
    int idx = blockIdx.x * 256 + threadIdx.x;
    if (idx >= 512 * 56) return;
    int c = idx / 56, o = idx - c * 56;
    float v = 0.f;
    if (o < 36) v = loc_w[o * 512 + c];
    else if (o < 54) v = score_w[(o - 36) * 512 + c];
    g_wh[idx] = v;
}

// ---------------------------------------------------------------------------
// 3x3 conv 1024->512 + bias + leaky relu (f32x2 packed, Kahan fold / 2 chunks)
// ---------------------------------------------------------------------------
__global__ void __launch_bounds__(256, 2) conv3_lrelu(const float* __restrict__ x,
                                                      const float* __restrict__ bias) {
    __shared__ __align__(16) float xs[8 * 4 * 72];
    __shared__ __align__(16) float ws[72 * 64];

    const int oc0 = blockIdx.x * 64;
    const int y0  = blockIdx.y * 2;
    const int tid = threadIdx.x;
    const int tx = tid & 15, ty = tid >> 4;
    const int ry  = tx >> 3;
    const int cx0 = (tx & 7) << 3;
    const int ocl = ty << 2;

    u64 part2[2][8], acc2[2][8], ncmp2[2][8];
#pragma unroll
    for (int o = 0; o < 2; ++o)
#pragma unroll
        for (int p = 0; p < 8; ++p) { part2[o][p] = 0ull; acc2[o][p] = 0ull; ncmp2[o][p] = 0ull; }

    const int x_ic0 = tid / 288;
    const int x_rem0 = tid - x_ic0 * 288;
    const int x_r0 = x_rem0 / 72;
    const int x_c0 = x_rem0 - x_r0 * 72;

#pragma unroll 1
    for (int chunk = 0; chunk < CIN / 8; ++chunk) {
        const int ic0 = chunk << 3;
        {
            int ic = x_ic0, r = x_r0, cc = x_c0;
            int sidx = tid;
#pragma unroll
            for (int l = 0; l < 9; ++l) {
                float v = 0.f;
                int iy  = y0 - 1 + r;
                int ixc = cc - 1;
                if (cc < 66 && (unsigned)iy < 64u && (unsigned)ixc < 64u)
                    v = x[(ic0 + ic) * 4096 + iy * 64 + ixc];
                xs[sidx] = v;
                sidx += 256;
                cc += 40; r += 3;
                if (cc >= 72) { cc -= 72; r += 1; }
                if (r >= 4) { r -= 4; ic += 1; }
            }
        }
        {
            const size_t base = (size_t)(ic0 * 9) * 512 + oc0;
#pragma unroll
            for (int l = 0; l < 18; ++l) {
                int idx = tid + l * 256;
                int k = idx >> 6, oc = idx & 63;
                ws[idx] = g_wt[base + (size_t)k * 512 + oc];
            }
        }
        __syncthreads();
#pragma unroll 1
        for (int ic = 0; ic < 8; ++ic) {
#pragma unroll
            for (int ky = 0; ky < 3; ++ky) {
                const float4* xr = (const float4*)&xs[ic * 288 + (ry + ky) * 72 + cx0];
                float xv[12];
                *(float4*)(xv)     = xr[0];
                *(float4*)(xv + 4) = xr[1];
                *(float4*)(xv + 8) = xr[2];
                u64 xb[10];
#pragma unroll
                for (int i = 0; i < 10; ++i) PK2(xb[i], xv[i], xv[i]);
#pragma unroll
                for (int kx = 0; kx < 3; ++kx) {
                    const float4 wq = *(const float4*)&ws[(ic * 9 + ky * 3 + kx) * 64 + ocl];
                    u64 wp0, wp1;
                    PK2(wp0, wq.x, wq.y);
                    PK2(wp1, wq.z, wq.w);
#pragma unroll
                    for (int p = 0; p < 8; ++p) {
                        FMA2(part2[0][p], wp0, xb[p + kx]);
                        FMA2(part2[1][p], wp1, xb[p + kx]);
                    }
                }
            }
        }
        __syncthreads();
        if (chunk & 1) {
#pragma unroll
            for (int o = 0; o < 2; ++o)
#pragma unroll
                for (int p = 0; p < 8; ++p) {
                    u64 y, t, s;
                    ADD2(y, part2[o][p], ncmp2[o][p]);
                    ADD2(t, acc2[o][p], y);
                    u64 tn = t ^ NEGMASK2;
                    ADD2(s, acc2[o][p], tn);
                    ADD2(ncmp2[o][p], s, y);
                    acc2[o][p] = t;
                    part2[o][p] = 0ull;
                }
        }
    }
    const int row = y0 + ry;
#pragma unroll
    for (int o = 0; o < 2; ++o)
#pragma unroll
        for (int p = 0; p < 8; ++p) {
            float a0, a1;
            UPK2(a0, a1, acc2[o][p]);
            int oc = oc0 + ocl + 2 * o;
            float v0 = a0 + bias[oc];
            float v1 = a1 + bias[oc + 1];
            v0 = v0 > 0.f ? v0 : 0.01f * v0;
            v1 = v1 > 0.f ? v1 : 0.01f * v1;
            g_h[oc * 4096 + row * 64 + cx0 + p] = v0;
            g_h[(oc + 1) * 4096 + row * 64 + cx0 + p] = v1;
        }
}

// ---------------------------------------------------------------------------
// 1x1 head convs: f32 per-chunk partials (64 taps) + Kahan-compensated fold
// ---------------------------------------------------------------------------
__global__ void __launch_bounds__(256) heads_kernel(float* __restrict__ out,
                                                    const float* __restrict__ loc_b,
                                                    const float* __restrict__ score_b) {
    __shared__ float hs[64 * 32];
    __shared__ float wsm[64 * 56];
    const int px0 = blockIdx.x * 32;
    const int tid = threadIdx.x;
    const int px = tid & 31, lane = tid >> 5;
    float acc[7], comp[7];
#pragma unroll
    for (int j = 0; j < 7; ++j) { acc[j] = 0.f; comp[j] = 0.f; }

    for (int ch = 0; ch < 8; ++ch) {
        const int c0 = ch * 64;
#pragma unroll
        for (int l = 0; l < 8; ++l) {
            int idx = tid + l * 256;
            int c = idx >> 5, pp = idx & 31;
            hs[idx] = g_h[(c0 + c) * 4096 + px0 + pp];
        }
#pragma unroll
        for (int l = 0; l < 14; ++l) {
            int idx = tid + l * 256;
            wsm[idx] = g_wh[c0 * 56 + idx];
        }
        __syncthreads();
        float part[7];
#pragma unroll
        for (int j = 0; j < 7; ++j) part[j] = 0.f;
#pragma unroll 4
        for (int c = 0; c < 64; ++c) {
            float hv = hs[c * 32 + px];
#pragma unroll
            for (int j = 0; j < 7; ++j)
                part[j] = __fmaf_rn(hv, wsm[c * 56 + lane * 7 + j], part[j]);
        }
        // Kahan fold of the 64-tap partial
#pragma unroll
        for (int j = 0; j < 7; ++j) {
            float y = __fsub_rn(part[j], comp[j]);
            float t = __fadd_rn(acc[j], y);
            comp[j] = __fsub_rn(__fsub_rn(t, acc[j]), y);
            acc[j] = t;
        }
        __syncthreads();
    }
    const int p = px0 + px;
#pragma unroll
    for (int j = 0; j < 7; ++j) {
        int o = lane * 7 + j;
        if (o < 36) {
            int a = o >> 2, cc = o & 3;
            out[OFF_LOC + (p * 9 + a) * 4 + cc] = acc[j] + loc_b[o];
        } else if (o < 54) {
            int s = o - 36;
            int a = s >> 1, cc = s & 1;
            out[OFF_SC + (p * 9 + a) * 2 + cc] = acc[j] + score_b[s];
        }
    }
}

// ---------------------------------------------------------------------------
__global__ void decode_kernel(float* __restrict__ out) {
    int idx = blockIdx.x * 256 + threadIdx.x;
    if (idx >= SORTN) return;
    if (idx >= NANCH) { g_keys[idx] = ~0ull; return; }

    int a = idx % 9;
    int p = idx / 9;
    int yy = p >> 6, xx = p & 63;

    const double ratios[3] = {0.5, 1.0, 2.0};
    const double scales[3] = {8.0, 16.0, 32.0};
    double r = ratios[a / 3], s = scales[a % 3];
    double hh = 16.0 * s * sqrt(r);
    double ww = 16.0 * s * sqrt(1.0 / r);
    float by1 = (float)(8.0 - hh / 2.0);
    float bx1 = (float)(8.0 - ww / 2.0);
    float by2 = (float)(8.0 + hh / 2.0);
    float bx2 = (float)(8.0 + ww / 2.0);
    float sy = (float)yy * 16.0f, sx = (float)xx * 16.0f;
    float a0 = sy + by1, a1 = sx + bx1, a2 = sy + by2, a3 = sx + bx2;

    out[OFF_ANC + idx * 4 + 0] = a0;
    out[OFF_ANC + idx * 4 + 1] = a1;
    out[OFF_ANC + idx * 4 + 2] = a2;
    out[OFF_ANC + idx * 4 + 3] = a3;

    float l0 = out[OFF_LOC + idx * 4 + 0];
    float l1 = out[OFF_LOC + idx * 4 + 1];
    float l2 = out[OFF_LOC + idx * 4 + 2];
    float l3 = out[OFF_LOC + idx * 4 + 3];
    float s0 = out[OFF_SC + idx * 2 + 0];
    float s1 = out[OFF_SC + idx * 2 + 1];

    double d0 = (double)s0, d1 = (double)s1;
    double m  = fmax(d0, d1);
    double e0 = exp(d0 - m), e1 = exp(d1 - m);
    float fg = (float)(e1 / (e0 + e1));

    float ha = a2 - a0, wa = a3 - a1;
    float cya = a0 + 0.5f * ha, cxa = a1 + 0.5f * wa;
    float cy = l0 * ha + cya;
    float cx = l1 * wa + cxa;
    float bh = ha * expf(l2);
    float bw = wa * expf(l3);
    g_boxes[idx * 4 + 0] = cy - 0.5f * bh;
    g_boxes[idx * 4 + 1] = cx - 0.5f * bw;
    g_boxes[idx * 4 + 2] = cy + 0.5f * bh;
    g_boxes[idx * 4 + 3] = cx + 0.5f * bw;

    unsigned ub = __float_as_uint(fg);
    g_keys[idx] = ((u64)(ub ^ 0xFFFFFFFFu) << 32) | (unsigned)idx;
}

// ---------------------------------------------------------------------------
// bitonic sort on 65536 u64 keys (R7-proven schedule)
// ---------------------------------------------------------------------------
__device__ __forceinline__ void cmpswap(u64& a, u64& b, bool up) {
    if ((a > b) == up) { u64 t = a; a = b; b = t; }
}

__global__ void __launch_bounds__(1024) bitonic_sort4k() {   // k <= 4096
    __shared__ u64 s[4096];
    const int base = blockIdx.x * 4096;
    const int t = threadIdx.x;
#pragma unroll
    for (int m = 0; m < 4; ++m) s[t + m * 1024] = g_keys[base + t + m * 1024];
    __syncthreads();
    for (int k = 2; k <= 4096; k <<= 1) {
        for (int j = k >> 1; j > 0; j >>= 1) {
#pragma unroll
            for (int m = 0; m < 2; ++m) {
                int pr = t + m * 1024;
                int i = ((pr & ~(j - 1)) << 1) | (pr & (j - 1));
                int p = i | j;
                bool up = (((base + i) & k) == 0);
                u64 a = s[i], b = s[p];
                if ((a > b) == up) { s[i] = b; s[p] = a; }
            }
            __syncthreads();
        }
    }
#pragma unroll
    for (int m = 0; m < 4; ++m) g_keys[base + t + m * 1024] = s[t + m * 1024];
}

__global__ void __launch_bounds__(1024) bitonic_merge4k(int k, int jstart) {
    __shared__ u64 s[4096];
    const int base = blockIdx.x * 4096;
    const int t = threadIdx.x;
#pragma unroll
    for (int m = 0; m < 4; ++m) s[t + m * 1024] = g_keys[base + t + m * 1024];
    __syncthreads();
    for (int j = jstart; j > 0; j >>= 1) {
#pragma unroll
        for (int m = 0; m < 2; ++m) {
            int pr = t + m * 1024;
            int i = ((pr & ~(j - 1)) << 1) | (pr & (j - 1));
            int p = i | j;
            bool up = (((base + i) & k) == 0);
            u64 a = s[i], b = s[p];
            if ((a > b) == up) { s[i] = b; s[p] = a; }
        }
        __syncthreads();
    }
#pragma unroll
    for (int m = 0; m < 4; ++m) g_keys[base + t + m * 1024] = s[t + m * 1024];
}

__global__ void __launch_bounds__(1024) bitonic_global2(int a, int k) {
    int q = blockIdx.x * 1024 + threadIdx.x;       // SORTN/4 threads
    int low = q & (a - 1);
    int i = ((q & ~(a - 1)) << 2) | low;
    u64 v0 = g_keys[i];
    u64 v1 = g_keys[i + a];
    u64 v2 = g_keys[i + 2 * a];
    u64 v3 = g_keys[i + 3 * a];
    bool up = ((i & k) == 0);
    cmpswap(v0, v2, up); cmpswap(v1, v3, up);
    cmpswap(v0, v1, up); cmpswap(v2, v3, up);
    g_keys[i] = v0;
    g_keys[i + a] = v1;
    g_keys[i + 2 * a] = v2;
    g_keys[i + 3 * a] = v3;
}

// ---------------------------------------------------------------------------
__global__ void gather_kernel(const int* __restrict__ imh, const int* __restrict__ imw) {
    int i = blockIdx.x * 256 + threadIdx.x;
    if (i >= NPRE) return;
    unsigned idx = (unsigned)g_keys[i];
    float H = (float)(*imh), W = (float)(*imw);
    float b0 = g_boxes[idx * 4 + 0];
    float b1 = g_boxes[idx * 4 + 1];
    float b2 = g_boxes[idx * 4 + 2];
    float b3 = g_boxes[idx * 4 + 3];
    b0 = fminf(fmaxf(b0, 0.f), H);
    b1 = fminf(fmaxf(b1, 0.f), W);
    b2 = fminf(fmaxf(b2, 0.f), H);
    b3 = fminf(fmaxf(b3, 0.f), W);
    g_sboxes[i * 4 + 0] = b0;
    g_sboxes[i * 4 + 1] = b1;
    g_sboxes[i * 4 + 2] = b2;
    g_sboxes[i * 4 + 3] = b3;
    g_valid[i] = ((b2 - b0) >= 16.f) && ((b3 - b1) >= 16.f);
}

// ---------------------------------------------------------------------------
// NMS bitmask: 256-thread blocks, 4 row-groups share one column tile
// ---------------------------------------------------------------------------
__global__ void __launch_bounds__(256) nms_mask() {
    const int colb = blockIdx.x;
    const int rowb4 = blockIdx.y;
    if (colb < rowb4 * 4) return;
    __shared__ __align__(16) float cb[64 * 4];
    const int cbase = colb * 64;
    const int cs = min(64, NPRE - cbase);
    const int t = threadIdx.x;
    if (t < cs) ((float4*)cb)[t] = ((const float4*)g_sboxes)[cbase + t];
    __syncthreads();
    const int rowb = rowb4 * 4 + (t >> 6);
    const int tr = t & 63;
    if (colb < rowb) return;
    const int i = rowb * 64 + tr;
    if (i >= NPRE) return;
    float y1 = g_sboxes[i * 4 + 0], x1 = g_sboxes[i * 4 + 1];
    float y2 = g_sboxes[i * 4 + 2], x2 = g_sboxes[i * 4 + 3];
    float ai = (y2 - y1) * (x2 - x1);
    u64 bits = 0;
    int j0 = (rowb == colb) ? (tr + 1) : 0;
    for (int j = j0; j < cs; ++j) {
        float cy1 = cb[j * 4 + 0], cx1 = cb[j * 4 + 1];
        float cy2 = cb[j * 4 + 2], cx2 = cb[j * 4 + 3];
        float yy1 = fmaxf(y1, cy1), xx1 = fmaxf(x1, cx1);
        float yy2 = fminf(y2, cy2), xx2 = fminf(x2, cx2);
        float inter = fmaxf(yy2 - yy1, 0.f) * fmaxf(xx2 - xx1, 0.f);
        float aj = (cy2 - cy1) * (cx2 - cx1);
        float iou = inter / (ai + aj - inter + 1e-10f);
        if (iou > 0.7f) bits |= (1ull << j);
    }
    g_mask[(size_t)i * NWORD + colb] = bits;
}

// ---------------------------------------------------------------------------
// greedy-NMS scan: batched updates (unroll 8) + roww prefetch + zero fill
// ---------------------------------------------------------------------------
__global__ void __launch_bounds__(256) nms_scan(float* __restrict__ out) {
    __shared__ u64 rem[NWORD];
    __shared__ u64 roww[64];
    __shared__ int selidx[64];
    const int t = threadIdx.x;
    for (int c = t; c < NWORD; c += 256) {
        u64 wv = 0;
        for (int b = 0; b < 64; ++b) {
            int i = c * 64 + b;
            if (i >= NPRE || !g_valid[i]) wv |= (1ull << b);
        }
        rem[c] = wv;
    }
    u64 nxt = 0;
    if (t < 64) nxt = g_mask[(size_t)t * NWORD + 0];
    __syncthreads();
    int cnt = 0;
    for (int c = 0; c < NWORD && cnt < NPOST; ++c) {
        if (t < 64) roww[t] = nxt;
        __syncthreads();
        u64 alive = ~rem[c];
        int ns = 0;
        while (alive && cnt < NPOST) {
            int b = __ffsll((long long)alive) - 1;
            int i = c * 64 + b;
            if (t < 4) out[OFF_ROIS + cnt * 4 + t] = g_sboxes[i * 4 + t];
            if (t == 0) selidx[ns] = i;
            ns++;
            cnt++;
            alive &= ~roww[b];
            alive &= ~(1ull << b);
        }
        __syncthreads();
        if (t < 64 && c + 1 < NWORD) {
            int ib = (c + 1) * 64 + t;
            nxt = (ib < NPRE) ? g_mask[(size_t)ib * NWORD + (c + 1)] : 0ull;
        }
        if (ns) {
            for (int wd = c + 1 + t; wd < NWORD; wd += 256) {
                u64 a = rem[wd];
                int k = 0;
                for (; k + 8 <= ns; k += 8) {
                    u64 m0 = g_mask[(size_t)selidx[k + 0] * NWORD + wd];
                    u64 m1 = g_mask[(size_t)selidx[k + 1] * NWORD + wd];
                    u64 m2 = g_mask[(size_t)selidx[k + 2] * NWORD + wd];
                    u64 m3 = g_mask[(size_t)selidx[k + 3] * NWORD + wd];
                    u64 m4 = g_mask[(size_t)selidx[k + 4] * NWORD + wd];
                    u64 m5 = g_mask[(size_t)selidx[k + 5] * NWORD + wd];
                    u64 m6 = g_mask[(size_t)selidx[k + 6] * NWORD + wd];
                    u64 m7 = g_mask[(size_t)selidx[k + 7] * NWORD + wd];
                    a |= ((m0 | m1) | (m2 | m3)) | ((m4 | m5) | (m6 | m7));
                }
                for (; k < ns; ++k)
                    a |= g_mask[(size_t)selidx[k] * NWORD + wd];
                rem[wd] = a;
            }
        }
        __syncthreads();
    }
    for (int i2 = cnt * 4 + t; i2 < NPOST * 4; i2 += 256)
        out[OFF_ROIS + i2] = 0.f;
}

// ---------------------------------------------------------------------------
extern "C" void kernel_launch(void* const* d_in, const int* in_sizes, int n_in,
                              void* d_out, int out_size) {
    const float* x       = (const float*)d_in[0];
    const float* conv_w  = (const float*)d_in[1];
    const float* conv_b  = (const float*)d_in[2];
    const float* score_w = (const float*)d_in[3];
    const float* score_b = (const float*)d_in[4];
    const float* loc_w   = (const float*)d_in[5];
    const float* loc_b   = (const float*)d_in[6];
    const int*   imh     = (const int*)d_in[7];
    const int*   imw     = (const int*)d_in[8];
    float* out = (float*)d_out;

    // my launch idx:    0          1        2        3 (= ncu idx 5 -> heads profiled)
    prep_wt<<<dim3(288, 16), 256>>>(conv_w);
    prep_w<<<(512 * 56 + 255) / 256, 256>>>(score_w, loc_w);
    conv3_lrelu<<<dim3(8, 32), 256>>>(x, conv_b);
    heads_kernel<<<128, 256>>>(out, loc_b, score_b);

    decode_kernel<<<SORTN / 256, 256>>>(out);

    bitonic_sort4k<<<16, 1024>>>();                       // k <= 4096
    bitonic_global2<<<16, 1024>>>(2048, 8192);            // k=8192: j=4096,2048
    bitonic_merge4k<<<16, 1024>>>(8192, 1024);            //          j=1024..1
    bitonic_global2<<<16, 1024>>>(4096, 16384);           // k=16384: j=8192,4096
    bitonic_merge4k<<<16, 1024>>>(16384, 2048);           //          j=2048..1
    bitonic_global2<<<16, 1024>>>(8192, 32768);           // k=32768: j=16384,8192
    bitonic_global2<<<16, 1024>>>(2048, 32768);           //          j=4096,2048
    bitonic_merge4k<<<16, 1024>>>(32768, 1024);           //          j=1024..1
    bitonic_global2<<<16, 1024>>>(16384, 65536);          // k=65536: j=32768,16384
    bitonic_global2<<<16, 1024>>>(4096, 65536);           //          j=8192,4096
    bitonic_merge4k<<<16, 1024>>>(65536, 2048);           //          j=2048..1

    gather_kernel<<<(NPRE + 255) / 256, 256>>>(imh, imw);
    nms_mask<<<dim3(NWORD, 47), 256>>>();
    nms_scan<<<1, 256>>>(out);
}

// round 11
// speedup vs baseline: 1.5816x; 1.5816x over previous
#include <cuda_runtime.h>
#include <math.h>

#define CIN   1024
#define COUT  512
#define NPIX  4096
#define NANCH 36864
#define SORTN 65536
#define NPRE  12000
#define NPOST 2000
#define NWORD 188   /* ceil(12000/64) */

#define OFF_LOC  0
#define OFF_SC   147456
#define OFF_ROIS 221184
#define OFF_ANC  229184

typedef unsigned long long u64;

__device__ __align__(16) float g_h[COUT * NPIX];        // conv output, 8 MB
__device__ __align__(16) float g_wt[9216 * 512];        // transposed conv weights [j][oc]
__device__ __align__(16) float g_wh[COUT * 56];         // transposed head weights
__device__ __align__(16) float g_boxes[NANCH * 4];      // decoded boxes
__device__ u64 g_keys[SORTN];                           // sort keys
__device__ __align__(16) float g_sboxes[NPRE * 4];      // clipped sorted boxes
__device__ int g_valid[NPRE];
__device__ u64 g_mask[(size_t)NPRE * NWORD];            // NMS bitmask, 18 MB

// packed f32x2 helpers
#define FMA2(d, a, b) asm("fma.rn.f32x2 %0, %1, %2, %0;" : "+l"(d) : "l"(a), "l"(b))
#define ADD2(d, a, b) asm("add.rn.f32x2 %0, %1, %2;" : "=l"(d) : "l"(a), "l"(b))
#define PK2(d, lo, hi) asm("mov.b64 %0, {%1, %2};" : "=l"(d) : "f"(lo), "f"(hi))
#define UPK2(lo, hi, s) asm("mov.b64 {%0, %1}, %2;" : "=f"(lo), "=f"(hi) : "l"(s))
#define NEGMASK2 0x8000000080000000ull

// ---------------------------------------------------------------------------
__global__ void zero_rois(float* __restrict__ out) {
    int i = blockIdx.x * 256 + threadIdx.x;
    if (i < NPOST * 4) out[OFF_ROIS + i] = 0.f;
}

// ---------------------------------------------------------------------------
// transpose conv weights: w[512][9216] -> g_wt[9216][512]
// ---------------------------------------------------------------------------
__global__ void __launch_bounds__(256) prep_wt(const float* __restrict__ w) {
    __shared__ float tile[32][33];
    const int j0  = blockIdx.x * 32;
    const int oc0 = blockIdx.y * 32;
    const int tx = threadIdx.x & 31, ty = threadIdx.x >> 5;
#pragma unroll
    for (int r = 0; r < 4; ++r)
        tile[ty + r * 8][tx] = w[(size_t)(oc0 + ty + r * 8) * 9216 + j0 + tx];
    __syncthreads();
#pragma unroll
    for (int r = 0; r < 4; ++r)
        g_wt[(size_t)(j0 + ty + r * 8) * 512 + oc0 + tx] = tile[tx][ty + r * 8];
}

// ---------------------------------------------------------------------------
__global__ void prep_w(const float* __restrict__ score_w, const float* __restrict__ loc_w) {
    int idx = blockIdx.x * 256 + threadIdx.x;
    if (idx >= 512 * 56) return;
    int c = idx / 56, o = idx - c * 56;
    float v = 0.f;
    if (o < 36) v = loc_w[o * 512 + c];
    else if (o < 54) v = score_w[(o - 36) * 512 + c];
    g_wh[idx] = v;
}

// ---------------------------------------------------------------------------
// 3x3 conv 1024->512 + bias + leaky relu (f32x2 packed, Kahan fold / 2 chunks)
// ---------------------------------------------------------------------------
__global__ void __launch_bounds__(256, 2) conv3_lrelu(const float* __restrict__ x,
                                                      const float* __restrict__ bias) {
    __shared__ __align__(16) float xs[8 * 4 * 72];
    __shared__ __align__(16) float ws[72 * 64];

    const int oc0 = blockIdx.x * 64;
    const int y0  = blockIdx.y * 2;
    const int tid = threadIdx.x;
    const int tx = tid & 15, ty = tid >> 4;
    const int ry  = tx >> 3;
    const int cx0 = (tx & 7) << 3;
    const int ocl = ty << 2;

    u64 part2[2][8], acc2[2][8], ncmp2[2][8];
#pragma unroll
    for (int o = 0; o < 2; ++o)
#pragma unroll
        for (int p = 0; p < 8; ++p) { part2[o][p] = 0ull; acc2[o][p] = 0ull; ncmp2[o][p] = 0ull; }

    const int x_ic0 = tid / 288;
    const int x_rem0 = tid - x_ic0 * 288;
    const int x_r0 = x_rem0 / 72;
    const int x_c0 = x_rem0 - x_r0 * 72;

#pragma unroll 1
    for (int chunk = 0; chunk < CIN / 8; ++chunk) {
        const int ic0 = chunk << 3;
        {
            int ic = x_ic0, r = x_r0, cc = x_c0;
            int sidx = tid;
#pragma unroll
            for (int l = 0; l < 9; ++l) {
                float v = 0.f;
                int iy  = y0 - 1 + r;
                int ixc = cc - 1;
                if (cc < 66 && (unsigned)iy < 64u && (unsigned)ixc < 64u)
                    v = x[(ic0 + ic) * 4096 + iy * 64 + ixc];
                xs[sidx] = v;
                sidx += 256;
                cc += 40; r += 3;
                if (cc >= 72) { cc -= 72; r += 1; }
                if (r >= 4) { r -= 4; ic += 1; }
            }
        }
        {
            const size_t base = (size_t)(ic0 * 9) * 512 + oc0;
#pragma unroll
            for (int l = 0; l < 18; ++l) {
                int idx = tid + l * 256;
                int k = idx >> 6, oc = idx & 63;
                ws[idx] = g_wt[base + (size_t)k * 512 + oc];
            }
        }
        __syncthreads();
#pragma unroll 1
        for (int ic = 0; ic < 8; ++ic) {
#pragma unroll
            for (int ky = 0; ky < 3; ++ky) {
                const float4* xr = (const float4*)&xs[ic * 288 + (ry + ky) * 72 + cx0];
                float xv[12];
                *(float4*)(xv)     = xr[0];
                *(float4*)(xv + 4) = xr[1];
                *(float4*)(xv + 8) = xr[2];
                u64 xb[10];
#pragma unroll
                for (int i = 0; i < 10; ++i) PK2(xb[i], xv[i], xv[i]);
#pragma unroll
                for (int kx = 0; kx < 3; ++kx) {
                    const float4 wq = *(const float4*)&ws[(ic * 9 + ky * 3 + kx) * 64 + ocl];
                    u64 wp0, wp1;
                    PK2(wp0, wq.x, wq.y);
                    PK2(wp1, wq.z, wq.w);
#pragma unroll
                    for (int p = 0; p < 8; ++p) {
                        FMA2(part2[0][p], wp0, xb[p + kx]);
                        FMA2(part2[1][p], wp1, xb[p + kx]);
                    }
                }
            }
        }
        __syncthreads();
        if (chunk & 1) {
#pragma unroll
            for (int o = 0; o < 2; ++o)
#pragma unroll
                for (int p = 0; p < 8; ++p) {
                    u64 y, t, s;
                    ADD2(y, part2[o][p], ncmp2[o][p]);
                    ADD2(t, acc2[o][p], y);
                    u64 tn = t ^ NEGMASK2;
                    ADD2(s, acc2[o][p], tn);
                    ADD2(ncmp2[o][p], s, y);
                    acc2[o][p] = t;
                    part2[o][p] = 0ull;
                }
        }
    }
    const int row = y0 + ry;
#pragma unroll
    for (int o = 0; o < 2; ++o)
#pragma unroll
        for (int p = 0; p < 8; ++p) {
            float a0, a1;
            UPK2(a0, a1, acc2[o][p]);
            int oc = oc0 + ocl + 2 * o;
            float v0 = a0 + bias[oc];
            float v1 = a1 + bias[oc + 1];
            v0 = v0 > 0.f ? v0 : 0.01f * v0;
            v1 = v1 > 0.f ? v1 : 0.01f * v1;
            g_h[oc * 4096 + row * 64 + cx0 + p] = v0;
            g_h[(oc + 1) * 4096 + row * 64 + cx0 + p] = v1;
        }
}

// ---------------------------------------------------------------------------
// 1x1 head convs: f32 per-chunk partials (64 taps) + Kahan-compensated fold
// ---------------------------------------------------------------------------
__global__ void __launch_bounds__(256) heads_kernel(float* __restrict__ out,
                                                    const float* __restrict__ loc_b,
                                                    const float* __restrict__ score_b) {
    __shared__ float hs[64 * 32];
    __shared__ float wsm[64 * 56];
    const int px0 = blockIdx.x * 32;
    const int tid = threadIdx.x;
    const int px = tid & 31, lane = tid >> 5;
    float acc[7], comp[7];
#pragma unroll
    for (int j = 0; j < 7; ++j) { acc[j] = 0.f; comp[j] = 0.f; }

    for (int ch = 0; ch < 8; ++ch) {
        const int c0 = ch * 64;
#pragma unroll
        for (int l = 0; l < 8; ++l) {
            int idx = tid + l * 256;
            int c = idx >> 5, pp = idx & 31;
            hs[idx] = g_h[(c0 + c) * 4096 + px0 + pp];
        }
#pragma unroll
        for (int l = 0; l < 14; ++l) {
            int idx = tid + l * 256;
            wsm[idx] = g_wh[c0 * 56 + idx];
        }
        __syncthreads();
        float part[7];
#pragma unroll
        for (int j = 0; j < 7; ++j) part[j] = 0.f;
#pragma unroll 4
        for (int c = 0; c < 64; ++c) {
            float hv = hs[c * 32 + px];
#pragma unroll
            for (int j = 0; j < 7; ++j)
                part[j] = __fmaf_rn(hv, wsm[c * 56 + lane * 7 + j], part[j]);
        }
#pragma unroll
        for (int j = 0; j < 7; ++j) {
            float y = __fsub_rn(part[j], comp[j]);
            float t = __fadd_rn(acc[j], y);
            comp[j] = __fsub_rn(__fsub_rn(t, acc[j]), y);
            acc[j] = t;
        }
        __syncthreads();
    }
    const int p = px0 + px;
#pragma unroll
    for (int j = 0; j < 7; ++j) {
        int o = lane * 7 + j;
        if (o < 36) {
            int a = o >> 2, cc = o & 3;
            out[OFF_LOC + (p * 9 + a) * 4 + cc] = acc[j] + loc_b[o];
        } else if (o < 54) {
            int s = o - 36;
            int a = s >> 1, cc = s & 1;
            out[OFF_SC + (p * 9 + a) * 2 + cc] = acc[j] + score_b[s];
        }
    }
}

// ---------------------------------------------------------------------------
__global__ void decode_kernel(float* __restrict__ out) {
    int idx = blockIdx.x * 256 + threadIdx.x;
    if (idx >= SORTN) return;
    if (idx >= NANCH) { g_keys[idx] = ~0ull; return; }

    int a = idx % 9;
    int p = idx / 9;
    int yy = p >> 6, xx = p & 63;

    const double ratios[3] = {0.5, 1.0, 2.0};
    const double scales[3] = {8.0, 16.0, 32.0};
    double r = ratios[a / 3], s = scales[a % 3];
    double hh = 16.0 * s * sqrt(r);
    double ww = 16.0 * s * sqrt(1.0 / r);
    float by1 = (float)(8.0 - hh / 2.0);
    float bx1 = (float)(8.0 - ww / 2.0);
    float by2 = (float)(8.0 + hh / 2.0);
    float bx2 = (float)(8.0 + ww / 2.0);
    float sy = (float)yy * 16.0f, sx = (float)xx * 16.0f;
    float a0 = sy + by1, a1 = sx + bx1, a2 = sy + by2, a3 = sx + bx2;

    out[OFF_ANC + idx * 4 + 0] = a0;
    out[OFF_ANC + idx * 4 + 1] = a1;
    out[OFF_ANC + idx * 4 + 2] = a2;
    out[OFF_ANC + idx * 4 + 3] = a3;

    float l0 = out[OFF_LOC + idx * 4 + 0];
    float l1 = out[OFF_LOC + idx * 4 + 1];
    float l2 = out[OFF_LOC + idx * 4 + 2];
    float l3 = out[OFF_LOC + idx * 4 + 3];
    float s0 = out[OFF_SC + idx * 2 + 0];
    float s1 = out[OFF_SC + idx * 2 + 1];

    double d0 = (double)s0, d1 = (double)s1;
    double m  = fmax(d0, d1);
    double e0 = exp(d0 - m), e1 = exp(d1 - m);
    float fg = (float)(e1 / (e0 + e1));

    float ha = a2 - a0, wa = a3 - a1;
    float cya = a0 + 0.5f * ha, cxa = a1 + 0.5f * wa;
    float cy = l0 * ha + cya;
    float cx = l1 * wa + cxa;
    float bh = ha * expf(l2);
    float bw = wa * expf(l3);
    g_boxes[idx * 4 + 0] = cy - 0.5f * bh;
    g_boxes[idx * 4 + 1] = cx - 0.5f * bw;
    g_boxes[idx * 4 + 2] = cy + 0.5f * bh;
    g_boxes[idx * 4 + 3] = cx + 0.5f * bw;

    unsigned ub = __float_as_uint(fg);
    g_keys[idx] = ((u64)(ub ^ 0xFFFFFFFFu) << 32) | (unsigned)idx;
}

// ---------------------------------------------------------------------------
// bitonic sort on 65536 u64 keys (R8-measured schedule, 9 launches)
// ---------------------------------------------------------------------------
__device__ __forceinline__ void cmpswap(u64& a, u64& b, bool up) {
    if ((a > b) == up) { u64 t = a; a = b; b = t; }
}

__global__ void __launch_bounds__(1024) bitonic_sort4k() {   // k <= 4096
    __shared__ u64 s[4096];
    const int base = blockIdx.x * 4096;
    const int t = threadIdx.x;
#pragma unroll
    for (int m = 0; m < 4; ++m) s[t + m * 1024] = g_keys[base + t + m * 1024];
    __syncthreads();
    for (int k = 2; k <= 4096; k <<= 1) {
        for (int j = k >> 1; j > 0; j >>= 1) {
#pragma unroll
            for (int m = 0; m < 2; ++m) {
                int pr = t + m * 1024;
                int i = ((pr & ~(j - 1)) << 1) | (pr & (j - 1));
                int p = i | j;
                bool up = (((base + i) & k) == 0);
                u64 a = s[i], b = s[p];
                if ((a > b) == up) { s[i] = b; s[p] = a; }
            }
            __syncthreads();
        }
    }
#pragma unroll
    for (int m = 0; m < 4; ++m) g_keys[base + t + m * 1024] = s[t + m * 1024];
}

__global__ void __launch_bounds__(1024) bitonic_merge4k(int k, int jstart) {
    __shared__ u64 s[4096];
    const int base = blockIdx.x * 4096;
    const int t = threadIdx.x;
#pragma unroll
    for (int m = 0; m < 4; ++m) s[t + m * 1024] = g_keys[base + t + m * 1024];
    __syncthreads();
    for (int j = jstart; j > 0; j >>= 1) {
#pragma unroll
        for (int m = 0; m < 2; ++m) {
            int pr = t + m * 1024;
            int i = ((pr & ~(j - 1)) << 1) | (pr & (j - 1));
            int p = i | j;
            bool up = (((base + i) & k) == 0);
            u64 a = s[i], b = s[p];
            if ((a > b) == up) { s[i] = b; s[p] = a; }
        }
        __syncthreads();
    }
#pragma unroll
    for (int m = 0; m < 4; ++m) g_keys[base + t + m * 1024] = s[t + m * 1024];
}

__global__ void __launch_bounds__(1024) bitonic_global2(int a, int k) {
    int q = blockIdx.x * 1024 + threadIdx.x;       // SORTN/4 threads
    int low = q & (a - 1);
    int i = ((q & ~(a - 1)) << 2) | low;
    u64 v0 = g_keys[i];
    u64 v1 = g_keys[i + a];
    u64 v2 = g_keys[i + 2 * a];
    u64 v3 = g_keys[i + 3 * a];
    bool up = ((i & k) == 0);
    cmpswap(v0, v2, up); cmpswap(v1, v3, up);
    cmpswap(v0, v1, up); cmpswap(v2, v3, up);
    g_keys[i] = v0;
    g_keys[i + a] = v1;
    g_keys[i + 2 * a] = v2;
    g_keys[i + 3 * a] = v3;
}

// fused four steps: j = 8a, 4a, 2a, a. 16 elems/thread in registers.
__global__ void __launch_bounds__(1024) bitonic_global4(int a, int k) {
    int q = blockIdx.x * 1024 + threadIdx.x;       // SORTN/16 threads
    int low = q & (a - 1);
    int i = ((q & ~(a - 1)) << 4) | low;
    u64 v[16];
#pragma unroll
    for (int m = 0; m < 16; ++m) v[m] = g_keys[i + m * a];
    bool up = ((i & k) == 0);
#pragma unroll
    for (int m = 0; m < 8; ++m) cmpswap(v[m], v[m + 8], up);
#pragma unroll
    for (int h = 0; h < 16; h += 8)
#pragma unroll
        for (int m = 0; m < 4; ++m) cmpswap(v[h + m], v[h + m + 4], up);
#pragma unroll
    for (int h = 0; h < 16; h += 4)
#pragma unroll
        for (int m = 0; m < 2; ++m) cmpswap(v[h + m], v[h + m + 2], up);
#pragma unroll
    for (int h = 0; h < 16; h += 2) cmpswap(v[h], v[h + 1], up);
#pragma unroll
    for (int m = 0; m < 16; ++m) g_keys[i + m * a] = v[m];
}

// ---------------------------------------------------------------------------
__global__ void gather_kernel(const int* __restrict__ imh, const int* __restrict__ imw) {
    int i = blockIdx.x * 256 + threadIdx.x;
    if (i >= NPRE) return;
    unsigned idx = (unsigned)g_keys[i];
    float H = (float)(*imh), W = (float)(*imw);
    float b0 = g_boxes[idx * 4 + 0];
    float b1 = g_boxes[idx * 4 + 1];
    float b2 = g_boxes[idx * 4 + 2];
    float b3 = g_boxes[idx * 4 + 3];
    b0 = fminf(fmaxf(b0, 0.f), H);
    b1 = fminf(fmaxf(b1, 0.f), W);
    b2 = fminf(fmaxf(b2, 0.f), H);
    b3 = fminf(fmaxf(b3, 0.f), W);
    g_sboxes[i * 4 + 0] = b0;
    g_sboxes[i * 4 + 1] = b1;
    g_sboxes[i * 4 + 2] = b2;
    g_sboxes[i * 4 + 3] = b3;
    g_valid[i] = ((b2 - b0) >= 16.f) && ((b3 - b1) >= 16.f);
}

// ---------------------------------------------------------------------------
// NMS bitmask: 256-thread blocks, 4 row-groups share one column tile
// ---------------------------------------------------------------------------
__global__ void __launch_bounds__(256) nms_mask() {
    const int colb = blockIdx.x;
    const int rowb4 = blockIdx.y;
    if (colb < rowb4 * 4) return;
    __shared__ __align__(16) float cb[64 * 4];
    const int cbase = colb * 64;
    const int cs = min(64, NPRE - cbase);
    const int t = threadIdx.x;
    if (t < cs) ((float4*)cb)[t] = ((const float4*)g_sboxes)[cbase + t];
    __syncthreads();
    const int rowb = rowb4 * 4 + (t >> 6);
    const int tr = t & 63;
    if (colb < rowb) return;
    const int i = rowb * 64 + tr;
    if (i >= NPRE) return;
    float y1 = g_sboxes[i * 4 + 0], x1 = g_sboxes[i * 4 + 1];
    float y2 = g_sboxes[i * 4 + 2], x2 = g_sboxes[i * 4 + 3];
    float ai = (y2 - y1) * (x2 - x1);
    u64 bits = 0;
    int j0 = (rowb == colb) ? (tr + 1) : 0;
    for (int j = j0; j < cs; ++j) {
        float cy1 = cb[j * 4 + 0], cx1 = cb[j * 4 + 1];
        float cy2 = cb[j * 4 + 2], cx2 = cb[j * 4 + 3];
        float yy1 = fmaxf(y1, cy1), xx1 = fmaxf(x1, cx1);
        float yy2 = fminf(y2, cy2), xx2 = fminf(x2, cx2);
        float inter = fmaxf(yy2 - yy1, 0.f) * fmaxf(xx2 - xx1, 0.f);
        float aj = (cy2 - cy1) * (cx2 - cx1);
        float iou = inter / (ai + aj - inter + 1e-10f);
        if (iou > 0.7f) bits |= (1ull << j);
    }
    g_mask[(size_t)i * NWORD + colb] = bits;
}

// ---------------------------------------------------------------------------
// greedy-NMS scan: batched updates (unroll 8) + roww prefetch + zero fill
// ---------------------------------------------------------------------------
__global__ void __launch_bounds__(256) nms_scan(float* __restrict__ out) {
    __shared__ u64 rem[NWORD];
    __shared__ u64 roww[64];
    __shared__ int selidx[64];
    const int t = threadIdx.x;
    for (int c = t; c < NWORD; c += 256) {
        u64 wv = 0;
        for (int b = 0; b < 64; ++b) {
            int i = c * 64 + b;
            if (i >= NPRE || !g_valid[i]) wv |= (1ull << b);
        }
        rem[c] = wv;
    }
    u64 nxt = 0;
    if (t < 64) nxt = g_mask[(size_t)t * NWORD + 0];
    __syncthreads();
    int cnt = 0;
    for (int c = 0; c < NWORD && cnt < NPOST; ++c) {
        if (t < 64) roww[t] = nxt;
        __syncthreads();
        u64 alive = ~rem[c];
        int ns = 0;
        while (alive && cnt < NPOST) {
            int b = __ffsll((long long)alive) - 1;
            int i = c * 64 + b;
            if (t < 4) out[OFF_ROIS + cnt * 4 + t] = g_sboxes[i * 4 + t];
            if (t == 0) selidx[ns] = i;
            ns++;
            cnt++;
            alive &= ~roww[b];
            alive &= ~(1ull << b);
        }
        __syncthreads();
        if (t < 64 && c + 1 < NWORD) {
            int ib = (c + 1) * 64 + t;
            nxt = (ib < NPRE) ? g_mask[(size_t)ib * NWORD + (c + 1)] : 0ull;
        }
        if (ns) {
            for (int wd = c + 1 + t; wd < NWORD; wd += 256) {
                u64 a = rem[wd];
                int k = 0;
                for (; k + 8 <= ns; k += 8) {
                    u64 m0 = g_mask[(size_t)selidx[k + 0] * NWORD + wd];
                    u64 m1 = g_mask[(size_t)selidx[k + 1] * NWORD + wd];
                    u64 m2 = g_mask[(size_t)selidx[k + 2] * NWORD + wd];
                    u64 m3 = g_mask[(size_t)selidx[k + 3] * NWORD + wd];
                    u64 m4 = g_mask[(size_t)selidx[k + 4] * NWORD + wd];
                    u64 m5 = g_mask[(size_t)selidx[k + 5] * NWORD + wd];
                    u64 m6 = g_mask[(size_t)selidx[k + 6] * NWORD + wd];
                    u64 m7 = g_mask[(size_t)selidx[k + 7] * NWORD + wd];
                    a |= ((m0 | m1) | (m2 | m3)) | ((m4 | m5) | (m6 | m7));
                }
                for (; k < ns; ++k)
                    a |= g_mask[(size_t)selidx[k] * NWORD + wd];
                rem[wd] = a;
            }
        }
        __syncthreads();
    }
    for (int i2 = cnt * 4 + t; i2 < NPOST * 4; i2 += 256)
        out[OFF_ROIS + i2] = 0.f;
}

// ---------------------------------------------------------------------------
extern "C" void kernel_launch(void* const* d_in, const int* in_sizes, int n_in,
                              void* d_out, int out_size) {
    const float* x       = (const float*)d_in[0];
    const float* conv_w  = (const float*)d_in[1];
    const float* conv_b  = (const float*)d_in[2];
    const float* score_w = (const float*)d_in[3];
    const float* score_b = (const float*)d_in[4];
    const float* loc_w   = (const float*)d_in[5];
    const float* loc_b   = (const float*)d_in[6];
    const int*   imh     = (const int*)d_in[7];
    const int*   imw     = (const int*)d_in[8];
    float* out = (float*)d_out;

    // my launch idx:    0          1        2        3 (= ncu idx 5 -> conv profiled)
    zero_rois<<<(NPOST * 4 + 255) / 256, 256>>>(out);
    prep_wt<<<dim3(288, 16), 256>>>(conv_w);
    prep_w<<<(512 * 56 + 255) / 256, 256>>>(score_w, loc_w);
    conv3_lrelu<<<dim3(8, 32), 256>>>(x, conv_b);

    heads_kernel<<<128, 256>>>(out, loc_b, score_b);
    decode_kernel<<<SORTN / 256, 256>>>(out);

    bitonic_sort4k<<<16, 1024>>>();                       // k <= 4096
    bitonic_global2<<<16, 1024>>>(2048, 8192);            // k=8192: j=4096,2048
    bitonic_merge4k<<<16, 1024>>>(8192, 1024);            //          j=1024..1
    bitonic_global2<<<16, 1024>>>(4096, 16384);           // k=16384: j=8192,4096
    bitonic_merge4k<<<16, 1024>>>(16384, 2048);           //          j=2048..1
    bitonic_global4<<<4, 1024>>>(2048, 32768);            // k=32768: j=16384..2048
    bitonic_merge4k<<<16, 1024>>>(32768, 1024);           //          j=1024..1
    bitonic_global4<<<4, 1024>>>(4096, 65536);            // k=65536: j=32768..4096
    bitonic_merge4k<<<16, 1024>>>(65536, 2048);           //          j=2048..1

    gather_kernel<<<(NPRE + 255) / 256, 256>>>(imh, imw);
    nms_mask<<<dim3(NWORD, 47), 256>>>();
    nms_scan<<<1, 256>>>(out);
}